// round 14
// baseline (speedup 1.0000x reference)
#include <cuda_runtime.h>
#include <cstdint>

#define TT 512
#define BB_ 64
#define HH 512
#define II 256
#define NG 2048  // 4*H

#define NCTA_REC 128
#define REC_THREADS 512
// smem floats: W 16384 | hA 8192 | hB 8192 | gA 512 | gB 512
#define REC_SMEM ((16384 + 8192 + 8192 + 512 + 512) * 4)

// 256 MB scratch for the precomputed input projection (sanctioned __device__ scratch).
__device__ float g_xg[(size_t)TT * BB_ * NG];
// 16 quarter-barrier counters: [chainid(4)][pair(4)], 64 arrivals per step each.
__device__ unsigned g_arrive[16];

static __device__ __forceinline__ unsigned ld_acq_gpu(unsigned* p) {
  unsigned v;
  asm volatile("ld.acquire.gpu.u32 %0, [%1];" : "=r"(v) : "l"(p) : "memory");
  return v;
}

static __device__ __forceinline__ void bar_sync(int id, int cnt) {
  asm volatile("bar.sync %0, %1;" :: "r"(id), "r"(cnt) : "memory");
}

static __device__ __forceinline__ float fast_sigmoid(float x) {
  return __fdividef(1.0f, 1.0f + __expf(-x));
}
static __device__ __forceinline__ float fast_tanh(float x) {
  float ax = fabsf(x);
  float e = __expf(-2.0f * ax);
  float r = __fdividef(1.0f - e, 1.0f + e);
  return copysignf(r, x);
}

// Packed dual-fp32 FMA (FFMA2): d = a*b + d elementwise on (lo,hi) pairs.
static __device__ __forceinline__ void fma2(unsigned long long& d,
                                            unsigned long long a,
                                            unsigned long long b) {
  asm("fma.rn.f32x2 %0, %1, %2, %0;" : "+l"(d) : "l"(a), "l"(b));
}

static __device__ __forceinline__ float2 unpack2(unsigned long long x) {
  float2 f;
  asm("mov.b64 {%0, %1}, %2;" : "=f"(f.x), "=f"(f.y) : "l"(x));
  return f;
}

static __device__ __forceinline__ unsigned long long dup2(float x) {
  unsigned long long r;
  asm("mov.b64 %0, {%1, %1};" : "=l"(r) : "f"(x));
  return r;
}

// 128-bit shared load straight into two b64 (k,k+1) pairs — no pack movs.
static __device__ __forceinline__ void lds_v2u64(unsigned long long& a,
                                                 unsigned long long& b,
                                                 uint32_t addr) {
  asm("ld.shared.v2.u64 {%0, %1}, [%2];" : "=l"(a), "=l"(b) : "r"(addr));
}

// ---------------------------------------------------------------------------
// Phase 1: xg[t*B+b, n] = sum_k x[t,b,k] * w_ih[n,k] + b_ih[n] + b_hh[n]
// 128x128x16 SGEMM tile, 256 threads, 8x8 micro-tile, FFMA2 inner product.
// Also resets the 16 chain-barrier counters (graph-replay determinism).
// ---------------------------------------------------------------------------
__global__ __launch_bounds__(256) void xg_gemm_kernel(
    const float* __restrict__ x, const float* __restrict__ w_ih,
    const float* __restrict__ b_ih, const float* __restrict__ b_hh) {
  if (blockIdx.x == 0 && blockIdx.y == 0 && threadIdx.x < 16)
    g_arrive[threadIdx.x] = 0u;

  __shared__ float Asm[16][132];
  __shared__ float Bsm[16][132];

  const int tid = threadIdx.x;
  const int tx = tid & 15;
  const int ty = tid >> 4;
  const int m0 = blockIdx.y * 128;
  const int n0 = blockIdx.x * 128;

  unsigned long long acc2[8][4];  // [m-row][n-pair]
#pragma unroll
  for (int i = 0; i < 8; ++i)
#pragma unroll
    for (int j = 0; j < 4; ++j) acc2[i][j] = 0ull;

  for (int k0 = 0; k0 < II; k0 += 16) {
#pragma unroll
    for (int r = 0; r < 2; ++r) {
      int idx = tid + r * 256;
      int m = idx >> 2;
      int kq = idx & 3;
      float4 v = *reinterpret_cast<const float4*>(
          &x[(size_t)(m0 + m) * II + k0 + kq * 4]);
      Asm[kq * 4 + 0][m] = v.x; Asm[kq * 4 + 1][m] = v.y;
      Asm[kq * 4 + 2][m] = v.z; Asm[kq * 4 + 3][m] = v.w;
      float4 w = *reinterpret_cast<const float4*>(
          &w_ih[(size_t)(n0 + m) * II + k0 + kq * 4]);
      Bsm[kq * 4 + 0][m] = w.x; Bsm[kq * 4 + 1][m] = w.y;
      Bsm[kq * 4 + 2][m] = w.z; Bsm[kq * 4 + 3][m] = w.w;
    }
    __syncthreads();
#pragma unroll
    for (int kk = 0; kk < 16; ++kk) {
      float4 a0 = *reinterpret_cast<const float4*>(&Asm[kk][ty * 4]);
      float4 a1 = *reinterpret_cast<const float4*>(&Asm[kk][64 + ty * 4]);
      ulonglong2 bq0 = *reinterpret_cast<const ulonglong2*>(&Bsm[kk][tx * 4]);
      ulonglong2 bq1 = *reinterpret_cast<const ulonglong2*>(&Bsm[kk][64 + tx * 4]);
      unsigned long long bp[4] = {bq0.x, bq0.y, bq1.x, bq1.y};
      float av[8] = {a0.x, a0.y, a0.z, a0.w, a1.x, a1.y, a1.z, a1.w};
#pragma unroll
      for (int i = 0; i < 8; ++i) {
        unsigned long long aa = dup2(av[i]);
#pragma unroll
        for (int j = 0; j < 4; ++j) fma2(acc2[i][j], aa, bp[j]);
      }
    }
    __syncthreads();
  }

  const float4* bi4 = reinterpret_cast<const float4*>(b_ih);
  const float4* bh4 = reinterpret_cast<const float4*>(b_hh);
  int nb = (n0 >> 2) + tx;
  float4 u0 = bi4[nb], v0 = bh4[nb];
  float4 u1 = bi4[nb + 16], v1 = bh4[nb + 16];
  float4 bias0 = make_float4(u0.x + v0.x, u0.y + v0.y, u0.z + v0.z, u0.w + v0.w);
  float4 bias1 = make_float4(u1.x + v1.x, u1.y + v1.y, u1.z + v1.z, u1.w + v1.w);

#pragma unroll
  for (int hm = 0; hm < 2; ++hm)
#pragma unroll
    for (int i = 0; i < 4; ++i) {
      int m = m0 + hm * 64 + ty * 4 + i;
      int mi = hm * 4 + i;
      float* dst = &g_xg[(size_t)m * NG + n0];
      float2 p0 = unpack2(acc2[mi][0]);
      float2 p1 = unpack2(acc2[mi][1]);
      float2 p2 = unpack2(acc2[mi][2]);
      float2 p3 = unpack2(acc2[mi][3]);
      float4 o0 = make_float4(p0.x + bias0.x, p0.y + bias0.y,
                              p1.x + bias0.z, p1.y + bias0.w);
      float4 o1 = make_float4(p2.x + bias1.x, p2.y + bias1.y,
                              p3.x + bias1.z, p3.y + bias1.w);
      *reinterpret_cast<float4*>(&dst[tx * 4]) = o0;
      *reinterpret_cast<float4*>(&dst[64 + tx * 4]) = o1;
    }
}

// ---------------------------------------------------------------------------
// Phase 2: persistent recurrence — TWO PHASE-DECOUPLED CHAINS PER CTA.
// 128 CTAs (1/SM), 512 threads. CTA = (j-block of 8) x (b-super of 32).
// Chain c (threads c*256..c*256+255, warps c*8..c*8+7) owns batch rows
// bsuper*32 + c*16 .. +15 END TO END: own hsm/gsm regions, own quarter
// barriers, own bar.sync ids. Chains share only the W smem slice (read-only
// after staging) and NEVER sync with each other -> their phases drift freely.
// SMSP s hosts warps {s, s+4} (chain A) and {s+8, s+12} (chain B): when one
// chain spins on its inter-CTA barrier or runs its serial reduce/act tail,
// the other chain's warps keep the FMA pipe fed.
// Within a chain: R12's proven pair pipeline (pair = 4 b-rows, ks=8 k-split,
// FFMA2 k-pair dot, 3-level reduce-scatter, act, per-pair global counter).
// ---------------------------------------------------------------------------
__global__ __launch_bounds__(REC_THREADS, 1) void lstm_rec_kernel(
    const float* __restrict__ h0, const float* __restrict__ c0,
    const float* __restrict__ w_hh, float* __restrict__ out) {
  extern __shared__ float sm[];
  float* Wsm = sm;  // 32 gate-rows x 512 k = 16384 floats

  const int tid = threadIdx.x;
  const int chain = tid >> 8;        // 0..1
  const int tc = tid & 255;          // thread within chain
  const int pair = tc >> 6;          // 0..3 (4 b-rows each)
  const int ptid = tc & 63;
  const int jblk = blockIdx.x & 63;  // 64 j-blocks of 8
  const int bsuper = blockIdx.x >> 6;
  const int j0 = jblk * 8;
  const int b0 = bsuper * 32 + chain * 16;
  const int chainid = bsuper * 2 + chain;
  unsigned* qbar = &g_arrive[chainid * 4 + pair];
  const int barid = 1 + chain * 4 + pair;

  float* hsm = sm + 16384 + chain * 8192;  // 16 rows x 512
  float* gsm = sm + 32768 + chain * 512;   // 128 outputs x 4 gates

  // --- stage W slice once: Wsm[(jl*4+g)*512 + k], rows n = g*512 + j0 + jl ---
  {
    const float4* w4 = reinterpret_cast<const float4*>(w_hh);
    float4* Wd = reinterpret_cast<float4*>(Wsm);
#pragma unroll
    for (int r = 0; r < 8; ++r) {
      int f4 = tid + r * REC_THREADS;  // 0..4095
      int row = f4 >> 7;               // jl*4+g, 0..31
      int col = f4 & 127;
      int jl = row >> 2, g = row & 3;
      Wd[f4] = w4[(size_t)(g * HH + j0 + jl) * (HH / 4) + col];
    }
  }

  const uint32_t hsm_u32 = (uint32_t)__cvta_generic_to_shared(hsm);
  const uint32_t wsm_u32 = (uint32_t)__cvta_generic_to_shared(Wsm);

  // dot-phase role: ptid = jt*8 + ks
  const int ks = ptid & 7;           // 8-way k-split
  const int jt = ptid >> 3;          // 0..7 = j within block

  // reduce-scatter ownership: lane ks keeps value-pair v_pair of the 8
  // (flat acc index v = i*4+g, pairs indexed by v>>1 = i*2 + (g>>1))
  const int v_pair = ((ks & 1) << 2) | (ks & 2) | ((ks >> 2) & 1);
  const int i_own = v_pair >> 1;     // b-row within pair
  const int gp_own = v_pair & 1;     // gate pair (0: gates 0,1; 1: gates 2,3)

  // activation role: ptid < 32 owns one (b,j) output of this pair
  const int bi_a = ptid >> 3;        // 0..3
  const int ji_a = ptid & 7;
  const int b_o = b0 + pair * 4 + bi_a;
  const int j_o = j0 + ji_a;
  const bool act = (ptid < 32);

  float creg = act ? c0[(size_t)b_o * HH + j_o] : 0.0f;

  float* hf = out + (size_t)TT * BB_ * HH;
  float* cf = hf + (size_t)BB_ * HH;

  __syncthreads();  // W staged before either chain proceeds

  for (int t = 0; t < TT; ++t) {
    // prefetch xg gates (overlaps spin + dot)
    float xg0 = 0.f, xg1 = 0.f, xg2 = 0.f, xg3 = 0.f;
    if (act) {
      const float* xrow = g_xg + ((size_t)t * BB_ + b_o) * NG + j_o;
      xg0 = xrow[0];
      xg1 = xrow[HH];
      xg2 = xrow[2 * HH];
      xg3 = xrow[3 * HH];
    }

    // wait for this pair's 4 h rows from all 64 CTAs of this chain
    if (t > 0) {
      const unsigned target = (unsigned)t * 64u;
      while (ld_acq_gpu(qbar) < target) {
      }
    }

    // copy this pair's 4 h rows into hsm (8 float4/thread, coalesced)
    {
      const float* hbase = (t == 0)
          ? h0
          : (out + (size_t)(t - 1) * BB_ * HH);
      const float4* s4 = reinterpret_cast<const float4*>(hbase) +
                         (size_t)(b0 + pair * 4) * (HH / 4);
      float4* d4 = reinterpret_cast<float4*>(hsm) + pair * 512;
#pragma unroll
      for (int r = 0; r < 8; ++r) d4[ptid + r * 64] = s4[ptid + r * 64];
    }
    bar_sync(barid, 64);

    // ---- dot: acc[i(4 b-rows)][g(4 gates)] of j-row jt, k-pair packed ----
    unsigned long long acc[16];
#pragma unroll
    for (int v = 0; v < 16; ++v) acc[v] = 0ull;

    const uint32_t hrow_base = hsm_u32 + (uint32_t)(pair * 4) * HH * 4u;
    const uint32_t wrow_base = wsm_u32 + (uint32_t)(jt * 4) * HH * 4u;

#pragma unroll 2
    for (int m = 0; m < 16; ++m) {
      const uint32_t kb = (uint32_t)(m * 32 + ks * 4);
      unsigned long long ha[4], hb[4];
#pragma unroll
      for (int i = 0; i < 4; ++i)
        lds_v2u64(ha[i], hb[i], hrow_base + (uint32_t)(i * HH + kb) * 4u);
#pragma unroll
      for (int g = 0; g < 4; ++g) {
        unsigned long long wa, wb;
        lds_v2u64(wa, wb, wrow_base + (uint32_t)(g * HH + kb) * 4u);
#pragma unroll
        for (int i = 0; i < 4; ++i) {
          fma2(acc[i * 4 + g], ha[i], wa);
          fma2(acc[i * 4 + g], hb[i], wb);
        }
      }
    }

    // collapse k-pairs, 3-level reduce-scatter over the 8 ks lanes
    float r[16];
#pragma unroll
    for (int v = 0; v < 16; ++v) {
      float2 f = unpack2(acc[v]);
      r[v] = f.x + f.y;
    }
    {
      const bool u1 = (ks & 1) != 0;
#pragma unroll
      for (int i = 0; i < 8; ++i) {
        float send = u1 ? r[i] : r[i + 8];
        float recv = __shfl_xor_sync(0xffffffffu, send, 1);
        float keep = u1 ? r[i + 8] : r[i];
        r[i] = keep + recv;
      }
      const bool u2 = (ks & 2) != 0;
#pragma unroll
      for (int i = 0; i < 4; ++i) {
        float send = u2 ? r[i] : r[i + 4];
        float recv = __shfl_xor_sync(0xffffffffu, send, 2);
        float keep = u2 ? r[i + 4] : r[i];
        r[i] = keep + recv;
      }
      const bool u3 = (ks & 4) != 0;
#pragma unroll
      for (int i = 0; i < 2; ++i) {
        float send = u3 ? r[i] : r[i + 2];
        float recv = __shfl_xor_sync(0xffffffffu, send, 4);
        float keep = u3 ? r[i + 2] : r[i];
        r[i] = keep + recv;
      }
    }
    // lane owns gates {gp_own*2, gp_own*2+1} of output (pair*4+i_own, jt)
    {
      const int o = (pair * 4 + i_own) * 8 + jt;
      *reinterpret_cast<float2*>(&gsm[o * 4 + gp_own * 2]) =
          make_float2(r[0], r[1]);
    }
    bar_sync(barid, 64);

    // ---- act: ptid<32, one output each, c stays in a register ----
    if (act) {
      float4 gv = *reinterpret_cast<const float4*>(
          &gsm[((pair * 4 + bi_a) * 8 + ji_a) * 4]);
      float ig = fast_sigmoid(gv.x + xg0);
      float fg = fast_sigmoid(gv.y + xg1);
      float tg = fast_tanh(gv.z + xg2);
      float og = fast_sigmoid(gv.w + xg3);
      float c = fg * creg + ig * tg;
      creg = c;
      float h = og * fast_tanh(c);

      out[(size_t)t * BB_ * HH + (size_t)b_o * HH + j_o] = h;
      if (t == TT - 1) {
        hf[(size_t)b_o * HH + j_o] = h;
        cf[(size_t)b_o * HH + j_o] = c;
      }
    }

    // pair arrives on its chain-quarter counter (h rows written & fenced)
    if (t != TT - 1) {
      __threadfence();
      bar_sync(barid, 64);
      if (ptid == 0) atomicAdd(qbar, 1u);
    }
  }
}

extern "C" void kernel_launch(void* const* d_in, const int* in_sizes, int n_in,
                              void* d_out, int out_size) {
  (void)in_sizes; (void)n_in; (void)out_size;
  const float* x    = (const float*)d_in[0];
  const float* h0   = (const float*)d_in[1];
  const float* c0   = (const float*)d_in[2];
  const float* w_ih = (const float*)d_in[3];
  const float* w_hh = (const float*)d_in[4];
  const float* b_ih = (const float*)d_in[5];
  const float* b_hh = (const float*)d_in[6];
  float* out = (float*)d_out;

  cudaFuncSetAttribute(lstm_rec_kernel,
                       cudaFuncAttributeMaxDynamicSharedMemorySize, REC_SMEM);

  // Phase 1: input projection for all timesteps (also resets barrier state)
  xg_gemm_kernel<<<dim3(NG / 128, (TT * BB_) / 128), 256>>>(x, w_ih, b_ih, b_hh);
  // Phase 2: persistent recurrence, 2 phase-decoupled chains per CTA
  lstm_rec_kernel<<<NCTA_REC, REC_THREADS, REC_SMEM>>>(h0, c0, w_hh, out);
}